// round 6
// baseline (speedup 1.0000x reference)
#include <cuda_runtime.h>
#include <cuda_bf16.h>

#define BT_TOK  65536
#define D_INV   512
#define D_EMBV  256
#define K_CODES 1024
#define N_BATCH 16
#define T_SEQ   4096

// ---------------- device scratch ---------------------------------------------
__device__ int           g_code[BT_TOK];
__device__ int           g_fixcnt;
__device__ int           g_fixlist[BT_TOK];
__device__ float         g_c2[K_CODES];
__device__ float         g_loss[N_BATCH];
__device__ __nv_bfloat16 g_wd_h[D_EMBV * D_INV];
__device__ __nv_bfloat16 g_wd_l[D_EMBV * D_INV];
__device__ __nv_bfloat16 g_cb_h[K_CODES * D_EMBV];
__device__ __nv_bfloat16 g_cb_l[K_CODES * D_EMBV];
__device__ __nv_bfloat16 g_zed_h[(size_t)BT_TOK * D_EMBV];
__device__ __nv_bfloat16 g_zed_l[(size_t)BT_TOK * D_EMBV];
__device__ float         g_cbup[K_CODES * D_INV];

// ---------------- helpers -------------------------------------------------------
static __device__ __forceinline__ unsigned smem_u32(const void* p) {
    unsigned a;
    asm("{ .reg .u64 t; cvta.to.shared.u64 t, %1; cvt.u32.u64 %0, t; }"
        : "=r"(a) : "l"(p));
    return a;
}

#define LDSM4(d, addr) \
    asm volatile("ldmatrix.sync.aligned.m8n8.x4.shared.b16 {%0,%1,%2,%3}, [%4];" \
        : "=r"((d)[0]), "=r"((d)[1]), "=r"((d)[2]), "=r"((d)[3]) : "r"(addr))

#define LDSM4B(b0, b1, addr) \
    asm volatile("ldmatrix.sync.aligned.m8n8.x4.shared.b16 {%0,%1,%2,%3}, [%4];" \
        : "=r"((b0)[0]), "=r"((b0)[1]), "=r"((b1)[0]), "=r"((b1)[1]) : "r"(addr))

#define MMA_B16(c, a, b) \
    asm volatile("mma.sync.aligned.m16n8k16.row.col.f32.bf16.bf16.f32 " \
        "{%0,%1,%2,%3},{%4,%5,%6,%7},{%8,%9},{%0,%1,%2,%3};" \
        : "+f"((c)[0]), "+f"((c)[1]), "+f"((c)[2]), "+f"((c)[3]) \
        : "r"((a)[0]), "r"((a)[1]), "r"((a)[2]), "r"((a)[3]), "r"((b)[0]), "r"((b)[1]))

static __device__ __forceinline__ unsigned pack_bf2(float x, float y) {
    __nv_bfloat162 t = __float22bfloat162_rn(make_float2(x, y));
    return *(unsigned*)&t;
}

// 2-way split: v -> hi, lo  (each uint2 = 4 bf16)
static __device__ __forceinline__ void split2_f4(float4 v, uint2& h, uint2& l) {
    __nv_bfloat162 h01 = __float22bfloat162_rn(make_float2(v.x, v.y));
    __nv_bfloat162 h23 = __float22bfloat162_rn(make_float2(v.z, v.w));
    float r0 = v.x - __bfloat162float(h01.x);
    float r1 = v.y - __bfloat162float(h01.y);
    float r2 = v.z - __bfloat162float(h23.x);
    float r3 = v.w - __bfloat162float(h23.y);
    h.x = *(unsigned*)&h01; h.y = *(unsigned*)&h23;
    l.x = pack_bf2(r0, r1); l.y = pack_bf2(r2, r3);
}

// ---------------- prep kernels ---------------------------------------------------
__global__ void k_prep(const float* __restrict__ wd, const float* __restrict__ cb) {
    int i = blockIdx.x * blockDim.x + threadIdx.x;
    if (i < D_EMBV * D_INV) {
        float x = wd[i];
        __nv_bfloat16 h = __float2bfloat16(x);
        g_wd_h[i] = h;
        g_wd_l[i] = __float2bfloat16(x - __bfloat162float(h));
    }
    int j = i - D_EMBV * D_INV;
    if (j >= 0 && j < K_CODES * D_EMBV) {
        float x = cb[j];
        __nv_bfloat16 h = __float2bfloat16(x);
        g_cb_h[j] = h;
        g_cb_l[j] = __float2bfloat16(x - __bfloat162float(h));
    }
}
__global__ void k_c2(const float* __restrict__ CB) {
    int k = blockIdx.x * blockDim.x + threadIdx.x;
    if (k < K_CODES) {
        const float* row = CB + (size_t)k * D_EMBV;
        float s = 0.f;
        #pragma unroll 8
        for (int e = 0; e < D_EMBV; e++) s += row[e] * row[e];
        g_c2[k] = s;
    }
}
__global__ void k_zero() {
    if (threadIdx.x < N_BATCH) g_loss[threadIdx.x] = 0.f;
    if (threadIdx.x == 31) g_fixcnt = 0;
}

// ---------------- CBup = codebook @ W_up^T (small fp32 SIMT GEMM) ----------------
static __device__ __forceinline__ unsigned long long bcast2(float x) {
    unsigned long long r; asm("mov.b64 %0, {%1, %1};" : "=l"(r) : "f"(x)); return r;
}
static __device__ __forceinline__ void fma2(unsigned long long& c, unsigned long long a,
                                            unsigned long long b) {
    asm("fma.rn.f32x2 %0, %1, %2, %0;" : "+l"(c) : "l"(a), "l"(b));
}
static __device__ __forceinline__ float2 unpack2(unsigned long long v) {
    float2 f;
    f.x = __uint_as_float((unsigned)(v & 0xffffffffull));
    f.y = __uint_as_float((unsigned)(v >> 32));
    return f;
}
__global__ void k_cbup(const float* __restrict__ A, const float* __restrict__ W) {
    __shared__ __align__(16) float As[32][68];
    __shared__ __align__(16) float Bs[32][68];
    const int m0 = blockIdx.x * 64, n0 = blockIdx.y * 64;
    const int tid = threadIdx.x, tx = tid & 15, ty = tid >> 4;
    unsigned long long acc[4][2];
    #pragma unroll
    for (int i = 0; i < 4; i++) { acc[i][0] = 0ull; acc[i][1] = 0ull; }
    for (int kk = 0; kk < D_EMBV; kk += 32) {
        #pragma unroll
        for (int i = 0; i < 8; i++) {
            int idx = tid + i * 256, r = idx >> 5, c = idx & 31;
            As[c][r] = A[(size_t)(m0 + r) * D_EMBV + kk + c];
            Bs[c][r] = W[(size_t)(n0 + r) * D_EMBV + kk + c];
        }
        __syncthreads();
        #pragma unroll
        for (int k = 0; k < 32; k++) {
            float4 av = *(const float4*)&As[k][ty * 4];
            ulonglong2 bv = *(const ulonglong2*)&Bs[k][tx * 4];
            unsigned long long a0 = bcast2(av.x), a1 = bcast2(av.y);
            unsigned long long a2 = bcast2(av.z), a3 = bcast2(av.w);
            fma2(acc[0][0], a0, bv.x); fma2(acc[0][1], a0, bv.y);
            fma2(acc[1][0], a1, bv.x); fma2(acc[1][1], a1, bv.y);
            fma2(acc[2][0], a2, bv.x); fma2(acc[2][1], a2, bv.y);
            fma2(acc[3][0], a3, bv.x); fma2(acc[3][1], a3, bv.y);
        }
        __syncthreads();
    }
    #pragma unroll
    for (int i = 0; i < 4; i++) {
        float2 p0 = unpack2(acc[i][0]), p1 = unpack2(acc[i][1]);
        *(float4*)&g_cbup[(size_t)(m0 + ty * 4 + i) * D_INV + n0 + tx * 4] =
            make_float4(p0.x, p0.y, p1.x, p1.y);
    }
}

// ---------------- k_down: zed = z_e @ Wd^T (2-way split, 3-pass HMMA) ------------
// buffer (40960B): Ah@0 Al@10240 Bh@20480 Bl@30720; x2 buffers. rows 80B.
#define KD_BUF 40960
#define KD_SMEM 81920
__global__ void __launch_bounds__(512, 1) k_down(const float* __restrict__ A,
                                                 float* __restrict__ C) {
    extern __shared__ __align__(16) char sm[];
    const unsigned sb = smem_u32(sm);
    const int tid = threadIdx.x, lane = tid & 31, wid = tid >> 5;
    const int wr = wid >> 2, wc = wid & 3;
    const int m0 = blockIdx.x * 128, n0 = blockIdx.y * 128;

    float acc[2][4][4];
    #pragma unroll
    for (int mi = 0; mi < 2; mi++)
        #pragma unroll
        for (int nj = 0; nj < 4; nj++)
            #pragma unroll
            for (int q = 0; q < 4; q++) acc[mi][nj][q] = 0.f;

    const int ar = tid >> 3, ac4 = tid & 7;        // A: 2 float4/thread via +512
    const int br = tid >> 2, bc = tid & 3;         // B: 1 uint4/thread per h/l

    float4 a4[2];
    uint4 b4h, b4l;
    // prefetch chunk 0
    #pragma unroll
    for (int i = 0; i < 2; i++) {
        int j = tid + i * 512, r = j >> 3, c4 = j & 7;
        a4[i] = *(const float4*)&A[(size_t)(m0 + r) * D_INV + c4 * 4];
    }
    b4h = *(const uint4*)&g_wd_h[(size_t)(n0 + br) * D_INV + bc * 8];
    b4l = *(const uint4*)&g_wd_l[(size_t)(n0 + br) * D_INV + bc * 8];
    {
        char* base = sm;
        #pragma unroll
        for (int i = 0; i < 2; i++) {
            int j = tid + i * 512, r = j >> 3, c4 = j & 7;
            uint2 h, l; split2_f4(a4[i], h, l);
            unsigned off = r * 80 + c4 * 8;
            *(uint2*)(base + off) = h;
            *(uint2*)(base + 10240 + off) = l;
        }
        unsigned off = br * 80 + bc * 16;
        *(uint4*)(base + 20480 + off) = b4h;
        *(uint4*)(base + 30720 + off) = b4l;
    }
    __syncthreads();

    #pragma unroll 1
    for (int ch = 0; ch < 16; ch++) {
        int nxt = ch + 1;
        if (nxt < 16) {
            #pragma unroll
            for (int i = 0; i < 2; i++) {
                int j = tid + i * 512, r = j >> 3, c4 = j & 7;
                a4[i] = *(const float4*)&A[(size_t)(m0 + r) * D_INV + nxt * 32 + c4 * 4];
            }
            b4h = *(const uint4*)&g_wd_h[(size_t)(n0 + br) * D_INV + nxt * 32 + bc * 8];
            b4l = *(const uint4*)&g_wd_l[(size_t)(n0 + br) * D_INV + nxt * 32 + bc * 8];
        }
        {
            unsigned bufb = sb + (ch & 1) * KD_BUF;
            #pragma unroll
            for (int s = 0; s < 2; s++) {
                unsigned a_h[2][4], a_l[2][4];
                #pragma unroll
                for (int mi = 0; mi < 2; mi++) {
                    unsigned off = (wr * 32 + mi * 16 + (lane & 15)) * 80 +
                                   ((lane >> 4) << 4) + s * 32;
                    LDSM4(a_h[mi], bufb + off);
                    LDSM4(a_l[mi], bufb + 10240 + off);
                }
                unsigned b_h[4][2], b_l[4][2];
                #pragma unroll
                for (int p = 0; p < 2; p++) {
                    unsigned off = (wc * 32 + p * 16 + (lane & 7) +
                                    ((lane >> 4) << 3)) * 80 +
                                   (((lane >> 3) & 1) << 4) + s * 32;
                    LDSM4B(b_h[p * 2], b_h[p * 2 + 1], bufb + 20480 + off);
                    LDSM4B(b_l[p * 2], b_l[p * 2 + 1], bufb + 30720 + off);
                }
                // 3 passes, interleaved (acc reuse distance = 8)
                #pragma unroll
                for (int mi = 0; mi < 2; mi++)
                    #pragma unroll
                    for (int k = 0; k < 4; k++) MMA_B16(acc[mi][k], a_h[mi], b_h[k]);
                #pragma unroll
                for (int mi = 0; mi < 2; mi++)
                    #pragma unroll
                    for (int k = 0; k < 4; k++) MMA_B16(acc[mi][k], a_l[mi], b_h[k]);
                #pragma unroll
                for (int mi = 0; mi < 2; mi++)
                    #pragma unroll
                    for (int k = 0; k < 4; k++) MMA_B16(acc[mi][k], a_h[mi], b_l[k]);
            }
        }
        if (nxt < 16) {
            char* base = sm + (nxt & 1) * KD_BUF;
            #pragma unroll
            for (int i = 0; i < 2; i++) {
                int j = tid + i * 512, r = j >> 3, c4 = j & 7;
                uint2 h, l; split2_f4(a4[i], h, l);
                unsigned off = r * 80 + c4 * 8;
                *(uint2*)(base + off) = h;
                *(uint2*)(base + 10240 + off) = l;
            }
            unsigned off = br * 80 + bc * 16;
            *(uint4*)(base + 20480 + off) = b4h;
            *(uint4*)(base + 30720 + off) = b4l;
        }
        __syncthreads();
    }

    // epilogue: write zed fp32 + pre-split bf16 hi/lo
    #pragma unroll
    for (int mi = 0; mi < 2; mi++)
        #pragma unroll
        for (int h = 0; h < 2; h++) {
            int row = m0 + wr * 32 + mi * 16 + h * 8 + (lane >> 2);
            #pragma unroll
            for (int nj = 0; nj < 4; nj++) {
                int col = n0 + wc * 32 + nj * 8 + 2 * (lane & 3);
                float v0 = acc[mi][nj][h * 2], v1 = acc[mi][nj][h * 2 + 1];
                *(float2*)&C[(size_t)row * D_EMBV + col] = make_float2(v0, v1);
                __nv_bfloat16 hx = __float2bfloat16(v0), hy = __float2bfloat16(v1);
                unsigned hp = ((unsigned)*(unsigned short*)&hy << 16) |
                              (unsigned)*(unsigned short*)&hx;
                unsigned lp = pack_bf2(v0 - __bfloat162float(hx),
                                       v1 - __bfloat162float(hy));
                size_t half = ((size_t)row * D_EMBV + col) >> 1;
                ((unsigned*)g_zed_h)[half] = hp;
                ((unsigned*)g_zed_l)[half] = lp;
            }
        }
}

// ---------------- k_dist: fused dist GEMM + top2 argmin (3-pass, streamed) ------
// buffer (40960B): Ah@0 Al@10240 Bh@20480 Bl@30720; x2 buffers.
// reduction tables at 81920: m1(2048) i1(2048) m2(2048) => 88064 total
#define DS_RED  81920
#define DS_SMEM 88064
__global__ void __launch_bounds__(512, 1) k_dist(float* __restrict__ code_f) {
    extern __shared__ __align__(16) char sm[];
    const unsigned sb = smem_u32(sm);
    const int tid = threadIdx.x, lane = tid & 31, wid = tid >> 5;
    const int wr = wid >> 2, wc = wid & 3;
    const int m0 = blockIdx.x * 128;
    const int r = tid >> 2, c = tid & 3;

    float acc[2][4][4];
    #pragma unroll
    for (int mi = 0; mi < 2; mi++)
        #pragma unroll
        for (int nj = 0; nj < 4; nj++)
            #pragma unroll
            for (int q = 0; q < 4; q++) acc[mi][nj][q] = 0.f;

    float t1[4], t2[4]; int ti[4];
    #pragma unroll
    for (int s = 0; s < 4; s++) { t1[s] = 3.4e38f; t2[s] = 3.4e38f; ti[s] = 0; }

    uint4 pah, pal, pbh, pbl;
    pah = *(const uint4*)&g_zed_h[(size_t)(m0 + r) * D_EMBV + c * 8];
    pal = *(const uint4*)&g_zed_l[(size_t)(m0 + r) * D_EMBV + c * 8];
    pbh = *(const uint4*)&g_cb_h[(size_t)r * D_EMBV + c * 8];
    pbl = *(const uint4*)&g_cb_l[(size_t)r * D_EMBV + c * 8];
    {
        unsigned off = r * 80 + c * 16;
        *(uint4*)(sm + off) = pah;
        *(uint4*)(sm + 10240 + off) = pal;
        *(uint4*)(sm + 20480 + off) = pbh;
        *(uint4*)(sm + 30720 + off) = pbl;
    }
    __syncthreads();

    #pragma unroll 1
    for (int it = 0; it < 64; it++) {
        int nt = it >> 3, kc = it & 7;
        int nxt = it + 1;
        if (nxt < 64) {
            int nnt = nxt >> 3, nkc = nxt & 7;
            pah = *(const uint4*)&g_zed_h[(size_t)(m0 + r) * D_EMBV + nkc * 32 + c * 8];
            pal = *(const uint4*)&g_zed_l[(size_t)(m0 + r) * D_EMBV + nkc * 32 + c * 8];
            pbh = *(const uint4*)&g_cb_h[(size_t)(nnt * 128 + r) * D_EMBV + nkc * 32 + c * 8];
            pbl = *(const uint4*)&g_cb_l[(size_t)(nnt * 128 + r) * D_EMBV + nkc * 32 + c * 8];
        }
        {
            unsigned bufb = sb + (it & 1) * KD_BUF;
            #pragma unroll
            for (int s = 0; s < 2; s++) {
                unsigned a_h[2][4], a_l[2][4];
                #pragma unroll
                for (int mi = 0; mi < 2; mi++) {
                    unsigned off = (wr * 32 + mi * 16 + (lane & 15)) * 80 +
                                   ((lane >> 4) << 4) + s * 32;
                    LDSM4(a_h[mi], bufb + off);
                    LDSM4(a_l[mi], bufb + 10240 + off);
                }
                unsigned b_h[4][2], b_l[4][2];
                #pragma unroll
                for (int p = 0; p < 2; p++) {
                    unsigned off = (wc * 32 + p * 16 + (lane & 7) +
                                    ((lane >> 4) << 3)) * 80 +
                                   (((lane >> 3) & 1) << 4) + s * 32;
                    LDSM4B(b_h[p * 2], b_h[p * 2 + 1], bufb + 20480 + off);
                    LDSM4B(b_l[p * 2], b_l[p * 2 + 1], bufb + 30720 + off);
                }
                #pragma unroll
                for (int mi = 0; mi < 2; mi++)
                    #pragma unroll
                    for (int k = 0; k < 4; k++) MMA_B16(acc[mi][k], a_h[mi], b_h[k]);
                #pragma unroll
                for (int mi = 0; mi < 2; mi++)
                    #pragma unroll
                    for (int k = 0; k < 4; k++) MMA_B16(acc[mi][k], a_l[mi], b_h[k]);
                #pragma unroll
                for (int mi = 0; mi < 2; mi++)
                    #pragma unroll
                    for (int k = 0; k < 4; k++) MMA_B16(acc[mi][k], a_h[mi], b_l[k]);
            }
        }
        if (kc == 7) {
            // fold distances for this 128-code tile into running top-2
            #pragma unroll
            for (int nj = 0; nj < 4; nj++)
                #pragma unroll
                for (int cc = 0; cc < 2; cc++) {
                    int g = nt * 128 + wc * 32 + nj * 8 + 2 * (lane & 3) + cc;
                    float c2v = __ldg(&g_c2[g]);
                    #pragma unroll
                    for (int mi = 0; mi < 2; mi++)
                        #pragma unroll
                        for (int h = 0; h < 2; h++) {
                            int slot = mi * 2 + h;
                            float d = c2v - 2.f * acc[mi][nj][h * 2 + cc];
                            if (d < t1[slot]) { t2[slot] = t1[slot]; t1[slot] = d; ti[slot] = g; }
                            else if (d < t2[slot]) { t2[slot] = d; }
                        }
                }
            #pragma unroll
            for (int mi = 0; mi < 2; mi++)
                #pragma unroll
                for (int nj = 0; nj < 4; nj++)
                    #pragma unroll
                    for (int q = 0; q < 4; q++) acc[mi][nj][q] = 0.f;
        }
        if (nxt < 64) {
            char* base = sm + (nxt & 1) * KD_BUF;
            unsigned off = r * 80 + c * 16;
            *(uint4*)(base + off) = pah;
            *(uint4*)(base + 10240 + off) = pal;
            *(uint4*)(base + 20480 + off) = pbh;
            *(uint4*)(base + 30720 + off) = pbl;
        }
        __syncthreads();
    }

    // quad-shuffle reduce (lanes 4k..4k+3 share a row)
    #pragma unroll
    for (int s = 0; s < 4; s++) {
        #pragma unroll
        for (int off = 1; off <= 2; off <<= 1) {
            float o1 = __shfl_xor_sync(0xffffffffu, t1[s], off);
            float o2 = __shfl_xor_sync(0xffffffffu, t2[s], off);
            int oi = __shfl_xor_sync(0xffffffffu, ti[s], off);
            bool takeo = (o1 < t1[s]) || (o1 == t1[s] && oi < ti[s]);
            float nm2 = takeo ? fminf(t1[s], o2) : fminf(t2[s], o1);
            if (takeo) { t1[s] = o1; ti[s] = oi; }
            t2[s] = nm2;
        }
    }
    float* red_m1 = (float*)(sm + DS_RED);
    int*   red_i1 = (int*)(sm + DS_RED + 2048);
    float* red_m2 = (float*)(sm + DS_RED + 4096);
    if ((lane & 3) == 0) {
        #pragma unroll
        for (int mi = 0; mi < 2; mi++)
            #pragma unroll
            for (int h = 0; h < 2; h++) {
                int s = mi * 2 + h;
                int row = wr * 32 + mi * 16 + h * 8 + (lane >> 2);
                red_m1[row * 4 + wc] = t1[s];
                red_i1[row * 4 + wc] = ti[s];
                red_m2[row * 4 + wc] = t2[s];
            }
    }
    __syncthreads();
    if (tid < 128) {
        float m1 = red_m1[tid * 4]; int i1 = red_i1[tid * 4]; float m2 = red_m2[tid * 4];
        #pragma unroll
        for (int x = 1; x < 4; x++) {
            float n1 = red_m1[tid * 4 + x], n2 = red_m2[tid * 4 + x];
            int ni = red_i1[tid * 4 + x];
            bool take = (n1 < m1) || (n1 == m1 && ni < i1);
            float nm2 = take ? fminf(m1, n2) : fminf(m2, n1);
            if (take) { m1 = n1; i1 = ni; }
            m2 = nm2;
        }
        int t = m0 + tid;
        g_code[t] = i1;
        code_f[t] = (float)i1;
        if (m2 - m1 < 0.1f) {
            int pos = atomicAdd(&g_fixcnt, 1);
            g_fixlist[pos] = t;
        }
    }
}

// ---------------- exact fp32 re-decide for flagged tokens ------------------------
// one block per list slot: recompute exact zed (z_e row x W_down) + full dist scan
__global__ void __launch_bounds__(256, 1) k_fix(const float* __restrict__ ZE,
                                                const float* __restrict__ WD,
                                                const float* __restrict__ CB,
                                                float* __restrict__ code_f) {
    __shared__ float ze[D_INV];
    __shared__ float zed[D_EMBV];
    __shared__ float bm[256];
    __shared__ int   bix[256];
    const int tid = threadIdx.x;
    const int cnt = g_fixcnt;
    for (int i = blockIdx.x; i < cnt; i += gridDim.x) {
        int t = g_fixlist[i];
        ze[tid] = ZE[(size_t)t * D_INV + tid];
        ze[tid + 256] = ZE[(size_t)t * D_INV + 256 + tid];
        __syncthreads();
        {
            const float* w = WD + (size_t)tid * D_INV;
            float s = 0.f;
            #pragma unroll 8
            for (int e = 0; e < D_INV; e++) s += ze[e] * w[e];
            zed[tid] = s;
        }
        __syncthreads();
        float best = 3.4e38f; int bi = 0;
        for (int k = tid; k < K_CODES; k += 256) {
            const float* cr = CB + (size_t)k * D_EMBV;
            float dot = 0.f;
            #pragma unroll 8
            for (int e = 0; e < D_EMBV; e++) dot += zed[e] * cr[e];
            float d = g_c2[k] - 2.f * dot;
            if (d < best) { best = d; bi = k; }
        }
        bm[tid] = best; bix[tid] = bi;
        __syncthreads();
        for (int off = 128; off > 0; off >>= 1) {
            if (tid < off) {
                float o = bm[tid + off]; int oi = bix[tid + off];
                if (o < bm[tid] || (o == bm[tid] && oi < bix[tid])) {
                    bm[tid] = o; bix[tid] = oi;
                }
            }
            __syncthreads();
        }
        if (tid == 0) { g_code[t] = bix[0]; code_f[t] = (float)bix[0]; }
        __syncthreads();
    }
}

// ---------------- gather: zq[t] = CBup[code[t]] ----------------------------------
__global__ void k_gather(float* __restrict__ ZQ) {
    int idx = blockIdx.x * blockDim.x + threadIdx.x;
    int t = idx >> 7, j = idx & 127;
    int code = g_code[t];
    ((float4*)ZQ)[(size_t)t * 128 + j] = ((const float4*)g_cbup)[(size_t)code * 128 + j];
}

// ---------------- per-batch VQ losses --------------------------------------------
__global__ void k_loss(const float* __restrict__ Z, const float* __restrict__ CB) {
    int lane = threadIdx.x & 31;
    int t = (blockIdx.x * blockDim.x + threadIdx.x) >> 5;
    int code = g_code[t];
    float s = 0.f;
    #pragma unroll
    for (int i = 0; i < 8; i++) {
        int e = lane + 32 * i;
        float d = Z[(size_t)t * D_EMBV + e] - CB[(size_t)code * D_EMBV + e];
        s += d * d;
    }
    #pragma unroll
    for (int o = 16; o > 0; o >>= 1) s += __shfl_xor_sync(0xffffffffu, s, o);
    if (lane == 0) atomicAdd(&g_loss[t >> 12], s);
}
__global__ void k_finish(float* __restrict__ oc, float* __restrict__ ob) {
    int i = threadIdx.x;
    if (i < N_BATCH) {
        float v = g_loss[i] * (1.0f / ((float)T_SEQ * (float)D_EMBV));
        oc[i] = v; ob[i] = v;
    }
}

// ---------------- launcher --------------------------------------------------------
extern "C" void kernel_launch(void* const* d_in, const int* in_sizes, int n_in,
                              void* d_out, int out_size) {
    const float* z_e    = (const float*)d_in[0];
    const float* cb     = (const float*)d_in[1];
    const float* w_down = (const float*)d_in[2];
    const float* w_up   = (const float*)d_in[3];

    float* out     = (float*)d_out;
    float* zq      = out;
    float* zed     = out + (size_t)BT_TOK * D_INV;
    float* codef   = out + (size_t)BT_TOK * (D_INV + D_EMBV);
    float* lcommit = codef + BT_TOK;
    float* lcb     = lcommit + N_BATCH;

    cudaFuncSetAttribute(k_down, cudaFuncAttributeMaxDynamicSharedMemorySize, KD_SMEM);
    cudaFuncSetAttribute(k_dist, cudaFuncAttributeMaxDynamicSharedMemorySize, DS_SMEM);

    k_prep<<<(D_EMBV * D_INV + K_CODES * D_EMBV + 255) / 256, 256>>>(w_down, cb);
    k_c2<<<(K_CODES + 255) / 256, 256>>>(cb);
    k_zero<<<1, 32>>>();
    k_cbup<<<dim3(K_CODES / 64, D_INV / 64), 256>>>(cb, w_up);
    k_down<<<dim3(BT_TOK / 128, 2), 512, KD_SMEM>>>(z_e, zed);
    k_dist<<<BT_TOK / 128, 512, DS_SMEM>>>(codef);
    k_fix<<<256, 256>>>(z_e, w_down, cb, codef);
    k_gather<<<(BT_TOK * 128) / 256, 256>>>(zq);
    k_loss<<<BT_TOK / 8, 256>>>(zed, cb);
    k_finish<<<1, 32>>>(lcommit, lcb);
}